// round 6
// baseline (speedup 1.0000x reference)
#include <cuda_runtime.h>
#include <cstdint>

// nu_grid_sampler: out[b,c,n] = x[b,c,px,py], x:(8,128,256,256) f32,
// coords:(8,32768,2) f32, out:(8,128,32768) f32.
//
// R6 = R5 structure (dense plane streaming, indices in regs, 1 block/SM,
// coalesced-predicated stores) with a DEEPER read pipeline: 8 stages x 32KB,
// 5-buffer ring (160KB smem), lookahead 4. R5's limiter was read-stream
// discontinuity (copies only issued in stages 0-1 of 4 -> DRAM duty ~55%).
// Now reads are issued through stage 4 and in flight until stage ~7.

#define GS_B 8
#define GS_C 128
#define GS_NX 256
#define GS_NY 256
#define GS_N 32768
#define GS_PIX (GS_NX * GS_NY)            // 65536
#define GS_HALF_N (GS_N / 2)              // 16384 pairs
#define STAGE_PIX 8192                     // pixels per stage (32KB)
#define NUM_STAGES 8
#define NUM_BUFS 5
#define LOOKAHEAD 4
#define K2_THREADS 1024
#define PAIRS_PER_THREAD (GS_HALF_N / K2_THREADS)  // 16

// g_pack[b*16384 + j] = idx(n=j) | (idx(n=j+16384) << 16)
__device__ unsigned int g_pack[GS_B * GS_HALF_N];   // 512 KB scratch

__device__ __forceinline__ unsigned int compute_idx(float cy, float cx) {
    float pxf = fminf(fmaxf(cx * (float)(GS_NX - 1), 0.0f), (float)GS_NX);
    float pyf = fminf(fmaxf(cy * (float)(GS_NY - 1), 0.0f), (float)GS_NY);
    int idx = (int)pxf * GS_NY + (int)pyf;
    return (unsigned int)min(idx, GS_PIX - 1);       // take_along_axis clamp
}

__global__ __launch_bounds__(256)
void idx_kernel(const float* __restrict__ coords) {
    int j = blockIdx.x * blockDim.x + threadIdx.x;   // 0..16383
    int b = blockIdx.y;
    const float2* cb = reinterpret_cast<const float2*>(coords) + (size_t)b * GS_N;
    float2 c_lo = cb[j];
    float2 c_hi = cb[j + GS_HALF_N];
    g_pack[b * GS_HALF_N + j] =
        compute_idx(c_lo.x, c_lo.y) | (compute_idx(c_hi.x, c_hi.y) << 16);
}

__device__ __forceinline__ void cp_async16(void* smem_dst, const void* gmem_src) {
    unsigned int s;
    asm("{ .reg .u64 t; cvta.to.shared.u64 t, %1; cvt.u32.u64 %0, t; }"
        : "=r"(s) : "l"(smem_dst));
    asm volatile("cp.async.cg.shared.global [%0], [%1], 16;\n" :: "r"(s), "l"(gmem_src));
}

// Copy one 8K-pixel stage (32KB): 2 rounds of 16B per thread. One commit group.
__device__ __forceinline__ void copy_stage(float* dst, const float* src, int tid) {
    #pragma unroll
    for (int q = 0; q < STAGE_PIX / (K2_THREADS * 4); ++q)       // 2 iters
        cp_async16(&dst[(q * K2_THREADS + tid) * 4],
                   &src[(q * K2_THREADS + tid) * 4]);
    asm volatile("cp.async.commit_group;\n");
}

__global__ __launch_bounds__(K2_THREADS, 1)
void gather_kernel(const float* __restrict__ x, float* __restrict__ out) {
    extern __shared__ float sbuf[];                  // 5 * STAGE_PIX floats = 160KB
    const int tid = threadIdx.x;
    const int bc  = blockIdx.x;                      // b*128 + c
    const int b   = bc >> 7;

    const float* __restrict__ plane = x + ((size_t)bc << 16);
    float* __restrict__ ob          = out + ((size_t)bc << 15);

    // Cache this thread's 16 packed index pairs in registers (coalesced reads).
    unsigned int pair[PAIRS_PER_THREAD];
    const unsigned int* __restrict__ pk = g_pack + b * GS_HALF_N + tid;
    #pragma unroll
    for (int k = 0; k < PAIRS_PER_THREAD; ++k)
        pair[k] = pk[k << 10];

    // Prologue: prefetch stages 0..3 (groups 0..3).
    #pragma unroll
    for (int p = 0; p < LOOKAHEAD; ++p)
        copy_stage(sbuf + (p % NUM_BUFS) * STAGE_PIX,
                   plane + (size_t)p * STAGE_PIX, tid);

    #pragma unroll
    for (int s = 0; s < NUM_STAGES; ++s) {
        // Issue copy for s+4 into buffer (s+4)%5. Safe: buffer (s+4)%5 was last
        // gathered at stage s-1, protected by the trailing __syncthreads.
        if (s + LOOKAHEAD < NUM_STAGES)
            copy_stage(sbuf + ((s + LOOKAHEAD) % NUM_BUFS) * STAGE_PIX,
                       plane + (size_t)(s + LOOKAHEAD) * STAGE_PIX, tid);

        // Wait until group s is complete (groups retire in order).
        if      (s < 4)  asm volatile("cp.async.wait_group 4;\n");
        else if (s == 4) asm volatile("cp.async.wait_group 3;\n");
        else if (s == 5) asm volatile("cp.async.wait_group 2;\n");
        else if (s == 6) asm volatile("cp.async.wait_group 1;\n");
        else             asm volatile("cp.async.wait_group 0;\n");
        __syncthreads();

        const float* cur = sbuf + (s % NUM_BUFS) * STAGE_PIX;
        const unsigned int us = (unsigned int)s;
        #pragma unroll
        for (int k = 0; k < PAIRS_PER_THREAD; ++k) {
            unsigned int pr = pair[k];
            unsigned int lo = pr & 0xFFFFu;
            unsigned int hi = pr >> 16;
            int j = tid + (k << 10);
            if ((lo >> 13) == us) ob[j]             = cur[lo & (STAGE_PIX - 1)];
            if ((hi >> 13) == us) ob[j + GS_HALF_N] = cur[hi & (STAGE_PIX - 1)];
        }
        __syncthreads();   // all gathers of stage s done before buf (s%5) is rewritten
    }
}

extern "C" void kernel_launch(void* const* d_in, const int* in_sizes, int n_in,
                              void* d_out, int out_size) {
    const float* x      = (const float*)d_in[0];   // (8,128,256,256) f32
    const float* coords = (const float*)d_in[1];   // (8,32768,2) f32
    float* out          = (float*)d_out;           // (8,128,32768) f32

    static int smem_set = 0;
    if (!smem_set) {
        cudaFuncSetAttribute(gather_kernel,
                             cudaFuncAttributeMaxDynamicSharedMemorySize,
                             NUM_BUFS * STAGE_PIX * sizeof(float));
        smem_set = 1;
    }

    idx_kernel<<<dim3(GS_HALF_N / 256, GS_B), 256>>>(coords);
    gather_kernel<<<GS_B * GS_C, K2_THREADS,
                    NUM_BUFS * STAGE_PIX * sizeof(float)>>>(x, out);
}

// round 7
// speedup vs baseline: 1.1849x; 1.1849x over previous
#include <cuda_runtime.h>
#include <cstdint>

// nu_grid_sampler: out[b,c,n] = x[b,c,px,py], x:(8,128,256,256) f32,
// coords:(8,32768,2) f32, out:(8,128,32768) f32.
//
// R7 = R5's proven structure (4 x 16K-pixel stages, 3x64KB smem ring,
// lookahead 2, indices in regs, predicated coalesced stores) made PERSISTENT:
// 128 blocks, each streams 8 consecutive planes (same batch -> index pairs
// loaded once). The cp.async pipeline rolls across plane boundaries, so the
// read stream never goes idle (R5's limiter: copies only issued during half
// of each block's lifetime -> DRAM duty ~56%).

#define GS_B 8
#define GS_C 128
#define GS_NX 256
#define GS_NY 256
#define GS_N 32768
#define GS_PIX (GS_NX * GS_NY)            // 65536
#define GS_HALF_N (GS_N / 2)              // 16384 pairs
#define STAGE_PIX 16384                    // 64KB per stage
#define STAGES_PER_PLANE 4
#define NUM_BUFS 3
#define K2_THREADS 1024
#define PAIRS_PER_THREAD (GS_HALF_N / K2_THREADS)  // 16
#define GRID_BLOCKS 128
#define PLANES_PER_BLOCK (GS_B * GS_C / GRID_BLOCKS)          // 8
#define TSTAGES (PLANES_PER_BLOCK * STAGES_PER_PLANE)          // 32

// g_pack[b*16384 + j] = idx(n=j) | (idx(n=j+16384) << 16)
__device__ unsigned int g_pack[GS_B * GS_HALF_N];   // 512 KB scratch

__device__ __forceinline__ unsigned int compute_idx(float cy, float cx) {
    float pxf = fminf(fmaxf(cx * (float)(GS_NX - 1), 0.0f), (float)GS_NX);
    float pyf = fminf(fmaxf(cy * (float)(GS_NY - 1), 0.0f), (float)GS_NY);
    int idx = (int)pxf * GS_NY + (int)pyf;
    return (unsigned int)min(idx, GS_PIX - 1);       // take_along_axis clamp
}

__global__ __launch_bounds__(256)
void idx_kernel(const float* __restrict__ coords) {
    int j = blockIdx.x * blockDim.x + threadIdx.x;   // 0..16383
    int b = blockIdx.y;
    const float2* cb = reinterpret_cast<const float2*>(coords) + (size_t)b * GS_N;
    float2 c_lo = cb[j];
    float2 c_hi = cb[j + GS_HALF_N];
    g_pack[b * GS_HALF_N + j] =
        compute_idx(c_lo.x, c_lo.y) | (compute_idx(c_hi.x, c_hi.y) << 16);
}

__device__ __forceinline__ void cp_async16(void* smem_dst, const void* gmem_src) {
    unsigned int s;
    asm("{ .reg .u64 t; cvta.to.shared.u64 t, %1; cvt.u32.u64 %0, t; }"
        : "=r"(s) : "l"(smem_dst));
    asm volatile("cp.async.cg.shared.global [%0], [%1], 16;\n" :: "r"(s), "l"(gmem_src));
}

// Copy one 16K-pixel stage (64KB): 4 rounds of 16B per thread. One group.
__device__ __forceinline__ void copy_stage(float* dst, const float* src, int tid) {
    #pragma unroll
    for (int q = 0; q < STAGE_PIX / (K2_THREADS * 4); ++q)       // 4 iters
        cp_async16(&dst[(q * K2_THREADS + tid) * 4],
                   &src[(q * K2_THREADS + tid) * 4]);
    asm volatile("cp.async.commit_group;\n");
}

__global__ __launch_bounds__(K2_THREADS, 1)
void gather_kernel(const float* __restrict__ x, float* __restrict__ out) {
    extern __shared__ float sbuf[];                  // 3 * 16384 floats = 192KB
    const int tid = threadIdx.x;
    const int base_plane = blockIdx.x * PLANES_PER_BLOCK;   // 8 planes, one batch
    const int b = base_plane >> 7;

    // All 8 planes share the batch's point set: load pairs ONCE.
    unsigned int pair[PAIRS_PER_THREAD];
    const unsigned int* __restrict__ pk = g_pack + b * GS_HALF_N + tid;
    #pragma unroll
    for (int k = 0; k < PAIRS_PER_THREAD; ++k)
        pair[k] = pk[k << 10];

    const float* __restrict__ xbase = x + ((size_t)base_plane << 16);

    // Prologue: prefetch global stages 0 and 1.
    copy_stage(sbuf + 0 * STAGE_PIX, xbase + 0 * (size_t)STAGE_PIX, tid);
    copy_stage(sbuf + 1 * STAGE_PIX, xbase + 1 * (size_t)STAGE_PIX, tid);

    #pragma unroll 1
    for (int t = 0; t < TSTAGES; ++t) {              // global stage index
        // Issue copy for stage t+2 (crosses plane boundaries seamlessly).
        if (t + 2 < TSTAGES)
            copy_stage(sbuf + ((t + 2) % NUM_BUFS) * STAGE_PIX,
                       xbase + (size_t)(t + 2) * STAGE_PIX, tid);

        if      (t + 2 < TSTAGES) asm volatile("cp.async.wait_group 2;\n");
        else if (t + 1 < TSTAGES) asm volatile("cp.async.wait_group 1;\n");
        else                      asm volatile("cp.async.wait_group 0;\n");
        __syncthreads();

        const float* cur = sbuf + (t % NUM_BUFS) * STAGE_PIX;
        const unsigned int us = (unsigned int)(t & 3);           // stage in plane
        float* __restrict__ ob = out + ((size_t)(base_plane + (t >> 2)) << 15);

        #pragma unroll
        for (int k = 0; k < PAIRS_PER_THREAD; ++k) {
            unsigned int pr = pair[k];
            unsigned int lo = pr & 0xFFFFu;
            unsigned int hi = pr >> 16;
            int j = tid + (k << 10);
            if ((lo >> 14) == us) ob[j]             = cur[lo & (STAGE_PIX - 1)];
            if ((hi >> 14) == us) ob[j + GS_HALF_N] = cur[hi & (STAGE_PIX - 1)];
        }
        __syncthreads();   // stage t fully read before buf (t%3) is rewritten at t+2
    }
}

extern "C" void kernel_launch(void* const* d_in, const int* in_sizes, int n_in,
                              void* d_out, int out_size) {
    const float* x      = (const float*)d_in[0];   // (8,128,256,256) f32
    const float* coords = (const float*)d_in[1];   // (8,32768,2) f32
    float* out          = (float*)d_out;           // (8,128,32768) f32

    static int smem_set = 0;
    if (!smem_set) {
        cudaFuncSetAttribute(gather_kernel,
                             cudaFuncAttributeMaxDynamicSharedMemorySize,
                             NUM_BUFS * STAGE_PIX * sizeof(float));
        smem_set = 1;
    }

    idx_kernel<<<dim3(GS_HALF_N / 256, GS_B), 256>>>(coords);
    gather_kernel<<<GRID_BLOCKS, K2_THREADS,
                    NUM_BUFS * STAGE_PIX * sizeof(float)>>>(x, out);
}

// round 8
// speedup vs baseline: 1.2955x; 1.0934x over previous
#include <cuda_runtime.h>
#include <cstdint>

// nu_grid_sampler: out[b,c,n] = x[b,c,px,py], x:(8,128,256,256) f32,
// coords:(8,32768,2) f32, out:(8,128,32768) f32.
//
// R8 = R5 (the proven 95us shape: 4 x 16K-pixel stages, 3 x 64KB smem ring,
// lookahead 2, 16 index pairs in registers, predicated coalesced stores,
// STATIC unroll) extended to 2 planes per block. The pipeline rolls across
// the plane boundary (8 combined stages), so cp.async issue stays active for
// stages 0..5 instead of 0..1 -> per-SM read duty ~0.55 -> ~0.8. Everything
// is compile-time static (R7's dynamic-loop overhead is what killed it).

#define GS_B 8
#define GS_C 128
#define GS_NX 256
#define GS_NY 256
#define GS_N 32768
#define GS_PIX (GS_NX * GS_NY)            // 65536
#define GS_HALF_N (GS_N / 2)              // 16384 pairs
#define STAGE_PIX 16384                    // 64KB per stage
#define NUM_BUFS 3
#define K2_THREADS 1024
#define PAIRS_PER_THREAD (GS_HALF_N / K2_THREADS)  // 16
#define PLANES_PER_BLOCK 2
#define TSTAGES 8                           // 2 planes x 4 stages
#define GRID_BLOCKS (GS_B * GS_C / PLANES_PER_BLOCK)   // 512

// g_pack[b*16384 + j] = idx(n=j) | (idx(n=j+16384) << 16)
__device__ unsigned int g_pack[GS_B * GS_HALF_N];   // 512 KB scratch

__device__ __forceinline__ unsigned int compute_idx(float cy, float cx) {
    float pxf = fminf(fmaxf(cx * (float)(GS_NX - 1), 0.0f), (float)GS_NX);
    float pyf = fminf(fmaxf(cy * (float)(GS_NY - 1), 0.0f), (float)GS_NY);
    int idx = (int)pxf * GS_NY + (int)pyf;
    return (unsigned int)min(idx, GS_PIX - 1);       // take_along_axis clamp
}

__global__ __launch_bounds__(256)
void idx_kernel(const float* __restrict__ coords) {
    int j = blockIdx.x * blockDim.x + threadIdx.x;   // 0..16383
    int b = blockIdx.y;
    const float2* cb = reinterpret_cast<const float2*>(coords) + (size_t)b * GS_N;
    float2 c_lo = cb[j];
    float2 c_hi = cb[j + GS_HALF_N];
    g_pack[b * GS_HALF_N + j] =
        compute_idx(c_lo.x, c_lo.y) | (compute_idx(c_hi.x, c_hi.y) << 16);
}

__device__ __forceinline__ void cp_async16(void* smem_dst, const void* gmem_src) {
    unsigned int s;
    asm("{ .reg .u64 t; cvta.to.shared.u64 t, %1; cvt.u32.u64 %0, t; }"
        : "=r"(s) : "l"(smem_dst));
    asm volatile("cp.async.cg.shared.global [%0], [%1], 16;\n" :: "r"(s), "l"(gmem_src));
}

// Copy one 16K-pixel stage (64KB): 4 rounds of 16B per thread. One group.
__device__ __forceinline__ void copy_stage(float* dst, const float* src, int tid) {
    #pragma unroll
    for (int q = 0; q < STAGE_PIX / (K2_THREADS * 4); ++q)       // 4 iters
        cp_async16(&dst[(q * K2_THREADS + tid) * 4],
                   &src[(q * K2_THREADS + tid) * 4]);
    asm volatile("cp.async.commit_group;\n");
}

__global__ __launch_bounds__(K2_THREADS, 1)
void gather_kernel(const float* __restrict__ x, float* __restrict__ out) {
    extern __shared__ float sbuf[];                  // 3 * 16384 floats = 192KB
    const int tid = threadIdx.x;
    const int base_plane = blockIdx.x * PLANES_PER_BLOCK;   // 2 planes, same batch
    const int b = base_plane >> 7;

    // Both planes share the batch's point set: load pairs once.
    unsigned int pair[PAIRS_PER_THREAD];
    const unsigned int* __restrict__ pk = g_pack + b * GS_HALF_N + tid;
    #pragma unroll
    for (int k = 0; k < PAIRS_PER_THREAD; ++k)
        pair[k] = pk[k << 10];

    const float* __restrict__ xbase = x + ((size_t)base_plane << 16);  // 512KB

    // Prologue: prefetch combined stages 0 and 1 (groups 0, 1).
    copy_stage(sbuf + 0 * STAGE_PIX, xbase + 0 * (size_t)STAGE_PIX, tid);
    copy_stage(sbuf + 1 * STAGE_PIX, xbase + 1 * (size_t)STAGE_PIX, tid);

    #pragma unroll
    for (int t = 0; t < TSTAGES; ++t) {              // fully static
        if (t + 2 < TSTAGES)
            copy_stage(sbuf + ((t + 2) % NUM_BUFS) * STAGE_PIX,
                       xbase + (size_t)(t + 2) * STAGE_PIX, tid);

        // Static wait ladder: keep 2 groups in flight mid-pipeline.
        if      (t + 2 < TSTAGES) asm volatile("cp.async.wait_group 2;\n");
        else if (t + 1 < TSTAGES) asm volatile("cp.async.wait_group 1;\n");
        else                      asm volatile("cp.async.wait_group 0;\n");
        __syncthreads();

        const float* cur = sbuf + (t % NUM_BUFS) * STAGE_PIX;     // static
        const unsigned int us = (unsigned int)(t & 3);            // static
        float* __restrict__ ob = out + ((size_t)(base_plane + (t >> 2)) << 15);

        #pragma unroll
        for (int k = 0; k < PAIRS_PER_THREAD; ++k) {
            unsigned int pr = pair[k];
            unsigned int lo = pr & 0xFFFFu;
            unsigned int hi = pr >> 16;
            int j = tid + (k << 10);
            if ((lo >> 14) == us) ob[j]             = cur[lo & (STAGE_PIX - 1)];
            if ((hi >> 14) == us) ob[j + GS_HALF_N] = cur[hi & (STAGE_PIX - 1)];
        }
        __syncthreads();   // stage t fully read before buf (t%3) rewritten at t+2
    }
}

extern "C" void kernel_launch(void* const* d_in, const int* in_sizes, int n_in,
                              void* d_out, int out_size) {
    const float* x      = (const float*)d_in[0];   // (8,128,256,256) f32
    const float* coords = (const float*)d_in[1];   // (8,32768,2) f32
    float* out          = (float*)d_out;           // (8,128,32768) f32

    static int smem_set = 0;
    if (!smem_set) {
        cudaFuncSetAttribute(gather_kernel,
                             cudaFuncAttributeMaxDynamicSharedMemorySize,
                             NUM_BUFS * STAGE_PIX * sizeof(float));
        smem_set = 1;
    }

    idx_kernel<<<dim3(GS_HALF_N / 256, GS_B), 256>>>(coords);
    gather_kernel<<<GRID_BLOCKS, K2_THREADS,
                    NUM_BUFS * STAGE_PIX * sizeof(float)>>>(x, out);
}

// round 9
// speedup vs baseline: 2.2678x; 1.7505x over previous
#include <cuda_runtime.h>
#include <cstdint>

// nu_grid_sampler: out[b,c,n] = x[b,c,px,py], x:(8,128,256,256) f32,
// coords:(8,32768,2) f32, out:(8,128,32768) f32.
//
// R9 = R5 structure (1024 blocks x 1 plane, 4 x 16K-pixel stages, 3 x 64KB
// smem ring, lookahead 2, 16 index pairs in regs, predicated coalesced
// stores) with the stage copy switched from 4096x16B cp.async (LDGSTS,
// rt=8cyc/op -> issue-bound at ~2.6TB/s chip reads; this was R5's hidden
// limiter) to ONE cp.async.bulk (TMA/UBLKCP) per stage + mbarrier
// complete_tx. Read issue cost vanishes; reads become DRAM-paced.

#define GS_B 8
#define GS_C 128
#define GS_NX 256
#define GS_NY 256
#define GS_N 32768
#define GS_PIX (GS_NX * GS_NY)            // 65536
#define GS_HALF_N (GS_N / 2)              // 16384 pairs
#define STAGE_PIX 16384                    // 64KB per stage
#define STAGE_BYTES (STAGE_PIX * 4)
#define NUM_STAGES 4
#define NUM_BUFS 3
#define K2_THREADS 1024
#define PAIRS_PER_THREAD (GS_HALF_N / K2_THREADS)  // 16

// g_pack[b*16384 + j] = idx(n=j) | (idx(n=j+16384) << 16)
__device__ unsigned int g_pack[GS_B * GS_HALF_N];   // 512 KB scratch

__device__ __forceinline__ unsigned int compute_idx(float cy, float cx) {
    float pxf = fminf(fmaxf(cx * (float)(GS_NX - 1), 0.0f), (float)GS_NX);
    float pyf = fminf(fmaxf(cy * (float)(GS_NY - 1), 0.0f), (float)GS_NY);
    int idx = (int)pxf * GS_NY + (int)pyf;
    return (unsigned int)min(idx, GS_PIX - 1);       // take_along_axis clamp
}

__global__ __launch_bounds__(256)
void idx_kernel(const float* __restrict__ coords) {
    int j = blockIdx.x * blockDim.x + threadIdx.x;   // 0..16383
    int b = blockIdx.y;
    const float2* cb = reinterpret_cast<const float2*>(coords) + (size_t)b * GS_N;
    float2 c_lo = cb[j];
    float2 c_hi = cb[j + GS_HALF_N];
    g_pack[b * GS_HALF_N + j] =
        compute_idx(c_lo.x, c_lo.y) | (compute_idx(c_hi.x, c_hi.y) << 16);
}

__device__ __forceinline__ uint32_t smem_u32(const void* p) {
    uint32_t a;
    asm("{ .reg .u64 t; cvta.to.shared.u64 t, %1; cvt.u32.u64 %0, t; }"
        : "=r"(a) : "l"(p));
    return a;
}

// Single-thread bulk copy of one 64KB stage with transaction-tracked mbarrier.
__device__ __forceinline__ void bulk_copy_stage(uint32_t smem_dst, const float* gsrc,
                                                uint32_t mbar) {
    asm volatile("mbarrier.arrive.expect_tx.shared.b64 _, [%0], %1;"
                 :: "r"(mbar), "r"((unsigned)STAGE_BYTES) : "memory");
    asm volatile("cp.async.bulk.shared::cta.global.mbarrier::complete_tx::bytes "
                 "[%0], [%1], %2, [%3];"
                 :: "r"(smem_dst), "l"(gsrc), "r"((unsigned)STAGE_BYTES), "r"(mbar)
                 : "memory");
}

__device__ __forceinline__ void mbar_wait(uint32_t mbar, unsigned phase) {
    asm volatile(
        "{\n\t"
        ".reg .pred P;\n\t"
        "LAB_WAIT_%=:\n\t"
        "mbarrier.try_wait.parity.acquire.cta.shared::cta.b64 P, [%0], %1, 0x989680;\n\t"
        "@P bra.uni LAB_DONE_%=;\n\t"
        "bra.uni LAB_WAIT_%=;\n\t"
        "LAB_DONE_%=:\n\t"
        "}"
        :: "r"(mbar), "r"(phase) : "memory");
}

__global__ __launch_bounds__(K2_THREADS, 1)
void gather_kernel(const float* __restrict__ x, float* __restrict__ out) {
    extern __shared__ float sbuf[];                  // 3 * 16384 floats = 192KB
    __shared__ __align__(8) unsigned long long mbar_store[NUM_BUFS];
    const int tid = threadIdx.x;
    const int bc  = blockIdx.x;                      // b*128 + c
    const int b   = bc >> 7;

    const float* __restrict__ plane = x + ((size_t)bc << 16);
    float* __restrict__ ob          = out + ((size_t)bc << 15);

    const uint32_t sb   = smem_u32(sbuf);
    const uint32_t mb0  = smem_u32(mbar_store);

    if (tid == 0) {
        #pragma unroll
        for (int q = 0; q < NUM_BUFS; ++q)
            asm volatile("mbarrier.init.shared.b64 [%0], 1;"
                         :: "r"(mb0 + q * 8) : "memory");
    }

    // Cache this thread's 16 packed index pairs in registers (coalesced).
    unsigned int pair[PAIRS_PER_THREAD];
    const unsigned int* __restrict__ pk = g_pack + b * GS_HALF_N + tid;
    #pragma unroll
    for (int k = 0; k < PAIRS_PER_THREAD; ++k)
        pair[k] = pk[k << 10];

    __syncthreads();   // mbarrier init visible to all before any TMA

    // Prologue: issue stages 0 and 1 (single thread, ~free).
    if (tid == 0) {
        bulk_copy_stage(sb + 0 * STAGE_BYTES, plane + 0 * (size_t)STAGE_PIX, mb0 + 0 * 8);
        bulk_copy_stage(sb + 1 * STAGE_BYTES, plane + 1 * (size_t)STAGE_PIX, mb0 + 1 * 8);
    }

    #pragma unroll
    for (int s = 0; s < NUM_STAGES; ++s) {
        // Issue stage s+2 into buf (s+2)%3 (= buf (s-1)%3, drained at the
        // trailing __syncthreads of stage s-1).
        if (tid == 0 && s + 2 < NUM_STAGES)
            bulk_copy_stage(sb + ((s + 2) % NUM_BUFS) * STAGE_BYTES,
                            plane + (size_t)(s + 2) * STAGE_PIX,
                            mb0 + ((s + 2) % NUM_BUFS) * 8);

        // Wait for stage s data (phase flips each time an mbar is reused).
        mbar_wait(mb0 + (s % NUM_BUFS) * 8, (unsigned)(s / NUM_BUFS));

        const float* cur = sbuf + (s % NUM_BUFS) * STAGE_PIX;
        const unsigned int us = (unsigned int)s;
        #pragma unroll
        for (int k = 0; k < PAIRS_PER_THREAD; ++k) {
            unsigned int pr = pair[k];
            unsigned int lo = pr & 0xFFFFu;
            unsigned int hi = pr >> 16;
            int j = tid + (k << 10);
            if ((lo >> 14) == us) ob[j]             = cur[lo & (STAGE_PIX - 1)];
            if ((hi >> 14) == us) ob[j + GS_HALF_N] = cur[hi & (STAGE_PIX - 1)];
        }
        __syncthreads();   // stage s fully read before buf (s%3) is rewritten
    }
}

extern "C" void kernel_launch(void* const* d_in, const int* in_sizes, int n_in,
                              void* d_out, int out_size) {
    const float* x      = (const float*)d_in[0];   // (8,128,256,256) f32
    const float* coords = (const float*)d_in[1];   // (8,32768,2) f32
    float* out          = (float*)d_out;           // (8,128,32768) f32

    static int smem_set = 0;
    if (!smem_set) {
        cudaFuncSetAttribute(gather_kernel,
                             cudaFuncAttributeMaxDynamicSharedMemorySize,
                             NUM_BUFS * STAGE_PIX * sizeof(float));
        smem_set = 1;
    }

    idx_kernel<<<dim3(GS_HALF_N / 256, GS_B), 256>>>(coords);
    gather_kernel<<<GS_B * GS_C, K2_THREADS,
                    NUM_BUFS * STAGE_PIX * sizeof(float)>>>(x, out);
}